// round 1
// baseline (speedup 1.0000x reference)
#include <cuda_runtime.h>
#include <cuda_bf16.h>

#define HH 512
#define WW 512
#define NPIX (HH * WW)
#define NITER 100
#define NBLK 148
#define NTHR 512
#define STRIDE (NBLK * NTHR)   // 75776
#define PPT 4                  // ceil(262144 / 75776)

// Persistent-kernel state. Zero-initialized at module load; kernel maintains
// invariants so every launch (correctness run + each graph replay) starts clean:
//  - g_count returns to 0 at the end of every barrier (last arriver resets it)
//  - g_epoch is monotonic; each block snapshots it at entry (safe: no release
//    can happen until ALL blocks have arrived at barrier 1, i.e. after snapshot)
//  - g_acc is zeroed by block 0 before barrier 1 each launch
__device__ double g_acc[NITER][4];
__device__ unsigned g_count;
__device__ volatile unsigned g_epoch;

__device__ __forceinline__ void gbar(unsigned k, unsigned base) {
    __syncthreads();
    if (threadIdx.x == 0) {
        __threadfence();
        unsigned old = atomicAdd(&g_count, 1u);
        if (old == (unsigned)gridDim.x - 1u) {
            *(volatile unsigned*)&g_count = 0u;   // no one touches count until release
            __threadfence();
            g_epoch = base + k;                   // release
        } else {
            while ((unsigned)(g_epoch - base) < k) { }
            __threadfence();
        }
    }
    __syncthreads();
}

// Bilinear sample with PyTorch grid_sample(zeros, align_corners=False) semantics,
// matching the reference's masked-gather formulation. Also returns d tr/d ix,
// d tr/d iy (gathered values are constants under autodiff).
__device__ __forceinline__ void sample(const float* __restrict__ mov,
                                       float ixf, float iyf,
                                       float& tr, float& dtdx, float& dtdy) {
    float x0f = floorf(ixf), y0f = floorf(iyf);
    float wx1 = ixf - x0f,   wy1 = iyf - y0f;
    float wx0 = 1.0f - wx1,  wy0 = 1.0f - wy1;
    float x1f = x0f + 1.0f,  y1f = y0f + 1.0f;
    bool bx0 = (x0f >= 0.0f) && (x0f <= 511.0f);
    bool bx1 = (x1f >= 0.0f) && (x1f <= 511.0f);
    bool by0 = (y0f >= 0.0f) && (y0f <= 511.0f);
    bool by1 = (y1f >= 0.0f) && (y1f <= 511.0f);
    int xi0 = (int)fminf(fmaxf(x0f, 0.0f), 511.0f);
    int xi1 = (int)fminf(fmaxf(x1f, 0.0f), 511.0f);
    int yi0 = (int)fminf(fmaxf(y0f, 0.0f), 511.0f);
    int yi1 = (int)fminf(fmaxf(y1f, 0.0f), 511.0f);
    float v00 = (bx0 && by0) ? __ldg(mov + yi0 * WW + xi0) : 0.0f;
    float v01 = (bx1 && by0) ? __ldg(mov + yi0 * WW + xi1) : 0.0f;
    float v10 = (bx0 && by1) ? __ldg(mov + yi1 * WW + xi0) : 0.0f;
    float v11 = (bx1 && by1) ? __ldg(mov + yi1 * WW + xi1) : 0.0f;
    float m0 = wx0 * v00 + wx1 * v01;
    float m1 = wx0 * v10 + wx1 * v11;
    tr   = wy0 * m0 + wy1 * m1;
    dtdx = wy0 * (v01 - v00) + wy1 * (v11 - v10);
    dtdy = m1 - m0;
}

__global__ void __launch_bounds__(NTHR, 1)
reg_kernel(const float* __restrict__ mov, const float* __restrict__ fix,
           const float* __restrict__ scale0, const float* __restrict__ rot0,
           const float* __restrict__ trans0, float* __restrict__ out) {
    __shared__ float shp[6];   // A = sc*c, B = sc*s, c, s, tx, ty
    __shared__ float red[16][4];

    const int tid = threadIdx.x;
    const int gid = blockIdx.x * NTHR + tid;

    unsigned base = 0;
    float cur_sc = 0.f, cur_r = 0.f, cur_tx = 0.f, cur_ty = 0.f;
    if (tid == 0) {
        base = g_epoch;              // snapshot before our first arrival
        cur_sc = scale0[0];
        cur_r  = rot0[0];
        cur_tx = trans0[0];
        cur_ty = trans0[1];
        float cc = cosf(cur_r), ss = sinf(cur_r);
        shp[0] = cur_sc * cc; shp[1] = cur_sc * ss;
        shp[2] = cc; shp[3] = ss; shp[4] = cur_tx; shp[5] = cur_ty;
    }
    if (blockIdx.x == 0) {
        for (int idx = tid; idx < NITER * 4; idx += NTHR)
            ((double*)g_acc)[idx] = 0.0;
    }

    // Iteration-invariant per-pixel data kept in registers.
    float pxj[PPT], pyv[PPT], pfx[PPT];
    bool pok[PPT];
#pragma unroll
    for (int k = 0; k < PPT; k++) {
        int p = gid + k * STRIDE;
        pok[k] = (p < NPIX);
        int pp = pok[k] ? p : 0;
        int i = pp >> 9, j = pp & 511;
        pxj[k] = ((float)j + 0.5f) * (2.0f / 512.0f) - 1.0f;
        pyv[k] = ((float)i + 0.5f) * (2.0f / 512.0f) - 1.0f;
        pfx[k] = fix[pp];
    }

    gbar(1, base);   // g_acc zeroed + initial shp visible within block

    for (int it = 0; it < NITER; it++) {
        float A = shp[0], B = shp[1], c = shp[2], s = shp[3];
        float tx = shp[4], ty = shp[5];

        float a0 = 0.f, a1 = 0.f, a2 = 0.f, a3 = 0.f; // d_scale, d_rot/sc, d_tx, d_ty
#pragma unroll
        for (int k = 0; k < PPT; k++) {
            if (!pok[k]) continue;
            float xj = pxj[k], yv = pyv[k];
            float gx = A * xj - B * yv + tx;
            float gy = B * xj + A * yv + ty;
            float ixf = ((gx + 1.0f) * 512.0f - 1.0f) * 0.5f;
            float iyf = ((gy + 1.0f) * 512.0f - 1.0f) * 0.5f;
            float tr, dtdx, dtdy;
            sample(mov, ixf, iyf, tr, dtdx, dtdy);
            float resid = tr - pfx[k];
            float dgxds = c * xj - s * yv;
            float dgyds = s * xj + c * yv;
            float rx = resid * dtdx;
            float ry = resid * dtdy;
            a2 += rx;
            a3 += ry;
            a0 += rx * dgxds + ry * dgyds;
            a1 += ry * dgxds - rx * dgyds;   // missing factor sc applied at update
        }

        // warp reduce (32 lanes)
#pragma unroll
        for (int off = 16; off > 0; off >>= 1) {
            a0 += __shfl_down_sync(0xFFFFFFFFu, a0, off);
            a1 += __shfl_down_sync(0xFFFFFFFFu, a1, off);
            a2 += __shfl_down_sync(0xFFFFFFFFu, a2, off);
            a3 += __shfl_down_sync(0xFFFFFFFFu, a3, off);
        }
        int wid = tid >> 5, lane = tid & 31;
        if (lane == 0) {
            red[wid][0] = a0; red[wid][1] = a1; red[wid][2] = a2; red[wid][3] = a3;
        }
        __syncthreads();
        if (tid < 16) {
            float b0 = red[tid][0], b1 = red[tid][1], b2 = red[tid][2], b3 = red[tid][3];
#pragma unroll
            for (int off = 8; off > 0; off >>= 1) {
                b0 += __shfl_down_sync(0x0000FFFFu, b0, off);
                b1 += __shfl_down_sync(0x0000FFFFu, b1, off);
                b2 += __shfl_down_sync(0x0000FFFFu, b2, off);
                b3 += __shfl_down_sync(0x0000FFFFu, b3, off);
            }
            if (tid == 0) {
                atomicAdd(&g_acc[it][0], (double)b0);   // RED.ADD.F64, return unused
                atomicAdd(&g_acc[it][1], (double)b1);
                atomicAdd(&g_acc[it][2], (double)b2);
                atomicAdd(&g_acc[it][3], (double)b3);
            }
        }

        gbar((unsigned)(it + 2), base);

        if (tid == 0) {
            double d0 = __ldcg(&g_acc[it][0]);
            double d1 = __ldcg(&g_acc[it][1]);
            double d2 = __ldcg(&g_acc[it][2]);
            double d3 = __ldcg(&g_acc[it][3]);
            // g = (2/N) * 256 * sum = sum / 512   (N = 512*512)
            float gs  = (float)(d0 * (1.0 / 512.0));
            float gr  = (float)(d1 * (double)cur_sc * (1.0 / 512.0));
            float gtx = (float)(d2 * (1.0 / 512.0));
            float gty = (float)(d3 * (1.0 / 512.0));
            cur_sc -= gs; cur_r -= gr; cur_tx -= gtx; cur_ty -= gty;  // LR = 1
            float cc = cosf(cur_r), ss = sinf(cur_r);
            shp[0] = cur_sc * cc; shp[1] = cur_sc * ss;
            shp[2] = cc; shp[3] = ss; shp[4] = cur_tx; shp[5] = cur_ty;
        }
        __syncthreads();
    }

    // Final transform with post-100-step params.
    {
        float A = shp[0], B = shp[1], tx = shp[4], ty = shp[5];
#pragma unroll
        for (int k = 0; k < PPT; k++) {
            if (!pok[k]) continue;
            int p = gid + k * STRIDE;
            float xj = pxj[k], yv = pyv[k];
            float gx = A * xj - B * yv + tx;
            float gy = B * xj + A * yv + ty;
            float ixf = ((gx + 1.0f) * 512.0f - 1.0f) * 0.5f;
            float iyf = ((gy + 1.0f) * 512.0f - 1.0f) * 0.5f;
            float tr, dtdx, dtdy;
            sample(mov, ixf, iyf, tr, dtdx, dtdy);
            out[p] = tr;
        }
    }
}

extern "C" void kernel_launch(void* const* d_in, const int* in_sizes, int n_in,
                              void* d_out, int out_size) {
    const float* mov   = (const float*)d_in[0];
    const float* fix   = (const float*)d_in[1];
    const float* scale = (const float*)d_in[2];
    const float* rot   = (const float*)d_in[3];
    const float* trans = (const float*)d_in[4];
    float* out = (float*)d_out;
    reg_kernel<<<NBLK, NTHR>>>(mov, fix, scale, rot, trans, out);
}